// round 14
// baseline (speedup 1.0000x reference)
#include <cuda_runtime.h>
#include <math.h>
#include <cstdint>

#define BB 2
#define NN 128
#define HH 128
#define OO 12
#define BDQ 32
#define LL 2
#define WFH 512
#define INQ 16

// ---------------- scratch (static device globals; no allocation) ------------
__device__ float g_ori[OO * 3];
__device__ float g_rotk[LL * OO * OO * HH];            // (L,P,O,H)
__device__ float g_h[BB * OO * NN * HH];               // (B,O,N,H) feature state
__device__ float g_hc[BB * NN * OO * HH];              // (B,M,O,H) conv output
__device__ float g_kb[(size_t)BB * NN * OO * NN * BDQ]; // (B,M,O,N,BD) ~50MB

// exact gelu (setup only, cold path)
__device__ __forceinline__ float gelu_exact(float x) {
    float x3 = x * x * x;
    float t = tanhf(0.7978845608028654f * (x + 0.044715f * x3));
    return 0.5f * x * (1.0f + t);
}

// fast gelu: MUFU tanh.approx (measured rel_err impact ~3e-7 end-to-end)
__device__ __forceinline__ float gelu_f(float x) {
    float x3 = x * x * x;
    float a = 0.7978845608028654f * (x + 0.044715f * x3);
    float t;
    asm("tanh.approx.f32 %0, %1;" : "=f"(t) : "f"(a));
    return 0.5f * x * (1.0f + t);
}

// ---- packed f32x2 helpers (FFMA2 path; ptxas won't emit from C++) ----------
__device__ __forceinline__ void fma2(unsigned long long& acc,
                                     unsigned long long a, unsigned long long b) {
    asm("fma.rn.f32x2 %0, %1, %2, %0;" : "+l"(acc) : "l"(a), "l"(b));
}
__device__ __forceinline__ unsigned long long pack2(float lo, float hi) {
    unsigned long long r;
    asm("mov.b64 %0, {%1, %2};" : "=l"(r) : "f"(lo), "f"(hi));
    return r;
}
__device__ __forceinline__ float2 unpack2(unsigned long long v) {
    float lo, hi;
    asm("mov.b64 {%0, %1}, %2;" : "=f"(lo), "=f"(hi) : "l"(v));
    return make_float2(lo, hi);
}

// ---- cp.async helpers -------------------------------------------------------
__device__ __forceinline__ void cp_async16(uint32_t dst_smem, const void* src) {
    asm volatile("cp.async.cg.shared.global [%0], [%1], 16;"
                 :: "r"(dst_smem), "l"(src));
}
__device__ __forceinline__ void cp_commit() {
    asm volatile("cp.async.commit_group;");
}
template <int N>
__device__ __forceinline__ void cp_wait() {
    asm volatile("cp.async.wait_group %0;" :: "n"(N));
}

__device__ __forceinline__ float blockReduceSum128(float val, float* red) {
    #pragma unroll
    for (int off = 16; off; off >>= 1)
        val += __shfl_down_sync(0xffffffffu, val, off);
    __syncthreads();
    if ((threadIdx.x & 31) == 0) red[threadIdx.x >> 5] = val;
    __syncthreads();
    return red[0] + red[1] + red[2] + red[3];
}

// ---------------- kernel A: ori, fiber basis, rot kernels -------------------
__global__ void setup_kernel(const float* __restrict__ W1r, const float* __restrict__ b1r,
                             const float* __restrict__ W2r, const float* __restrict__ b2r,
                             const float* __restrict__ Wrot) {
    __shared__ float fb_sh[OO * OO * BDQ];   // fiber basis (P,O,BD)
    int t = threadIdx.x;                     // 256 threads

    if (t < OO) {
        float fi = (float)t;
        const float PI_F  = 3.14159265358979323846f;
        const float C_F   = 3.23606797749978969641f;   // 1+sqrt(5) in f32
        const float TWOPI = 6.28318530717958647692f;
        float theta = fmodf((PI_F * fi) * C_F, TWOPI);
        float phi = acosf(1.0f - 2.0f * (fi + 0.5f) / 12.0f);
        float sp = sinf(phi);
        g_ori[t * 3 + 0] = sp * cosf(theta);
        g_ori[t * 3 + 1] = sp * sinf(theta);
        g_ori[t * 3 + 2] = cosf(phi);
    }
    __syncthreads();

    if (t < OO * OO) {
        int p = t / OO, o = t % OO;
        float tt = g_ori[p * 3 + 0] * g_ori[o * 3 + 0]
                 + g_ori[p * 3 + 1] * g_ori[o * 3 + 1]
                 + g_ori[p * 3 + 2] * g_ori[o * 3 + 2];
        float f0 = tt, f1 = tt * tt, f2 = f1 * tt;
        float acc[BDQ];
        #pragma unroll
        for (int d = 0; d < BDQ; d++) acc[d] = 0.0f;
        for (int j = 0; j < HH; j++) {
            float hj = gelu_exact(b1r[j] + f0 * W1r[0 * HH + j]
                                         + f1 * W1r[1 * HH + j]
                                         + f2 * W1r[2 * HH + j]);
            #pragma unroll
            for (int d = 0; d < BDQ; d++) acc[d] += hj * W2r[j * BDQ + d];
        }
        #pragma unroll
        for (int d = 0; d < BDQ; d++)
            fb_sh[t * BDQ + d] = gelu_exact(acc[d] + b2r[d]);
    }
    __syncthreads();

    for (int idx = t; idx < LL * OO * OO * HH; idx += blockDim.x) {
        int c = idx % HH;
        int rest = idx / HH;
        int o = rest % OO; rest /= OO;
        int p = rest % OO;
        int l = rest / OO;
        float s = 0.0f;
        #pragma unroll
        for (int d = 0; d < BDQ; d++)
            s += fb_sh[(p * OO + o) * BDQ + d] * Wrot[(l * BDQ + d) * HH + c];
        g_rotk[idx] = s;
    }
}

// ---------------- kernel B: h0 = x @ We, broadcast over O -------------------
__global__ void embed_kernel(const float* __restrict__ x, const float* __restrict__ We) {
    int n = blockIdx.x, b = blockIdx.y, c = threadIdx.x;
    __shared__ float xs[INQ];
    if (c < INQ) xs[c] = x[(b * NN + n) * INQ + c];
    __syncthreads();
    float s = 0.0f;
    #pragma unroll
    for (int k = 0; k < INQ; k++) s += xs[k] * We[k * HH + c];
    #pragma unroll
    for (int o = 0; o < OO; o++)
        g_h[((b * OO + o) * NN + n) * HH + c] = s;
}

// ---------------- kernel C: kernel basis MLP (2 o per block, f32x2 acc) -----
__global__ void __launch_bounds__(128)
kbasis_kernel(const float* __restrict__ pos,
              const float* __restrict__ W1s, const float* __restrict__ b1s,
              const float* __restrict__ W2s, const float* __restrict__ b2s) {
    int op = blockIdx.x, m = blockIdx.y, b = blockIdx.z;
    int o0 = op * 2, o1 = op * 2 + 1;
    int n = threadIdx.x;

    __shared__ __align__(16) float w1c[HH * 12];   // folded weights, 12-padded
    __shared__ float bb1[HH];
    __shared__ __align__(16) float w2[HH * BDQ];
    __shared__ float bb2[BDQ];

    // fold W1s (14 x 128) -> w1c (128 x 9, pad 12); thread n owns row j=n
    {
        int j = n;
        w1c[j * 12 + 0] = W1s[0 * HH + j];                                   // a
        w1c[j * 12 + 1] = W1s[1 * HH + j];                                   // b
        w1c[j * 12 + 2] = W1s[2 * HH + j];                                   // a^2
        w1c[j * 12 + 3] = W1s[3 * HH + j] + W1s[4 * HH + j];                 // ab (+ba)
        w1c[j * 12 + 4] = W1s[5 * HH + j];                                   // b^2
        w1c[j * 12 + 5] = W1s[6 * HH + j];                                   // a^3
        w1c[j * 12 + 6] = W1s[7 * HH + j] + W1s[8 * HH + j] + W1s[10 * HH + j];  // a^2 b
        w1c[j * 12 + 7] = W1s[9 * HH + j] + W1s[11 * HH + j] + W1s[12 * HH + j]; // a b^2
        w1c[j * 12 + 8] = W1s[13 * HH + j];                                  // b^3
        w1c[j * 12 + 9] = 0.0f; w1c[j * 12 + 10] = 0.0f; w1c[j * 12 + 11] = 0.0f;
    }
    bb1[n] = b1s[n];
    for (int i = n; i < HH * BDQ; i += 128) w2[i] = W2s[i];
    if (n < BDQ) bb2[n] = b2s[n];
    __syncthreads();

    float px = pos[(b * NN + m) * 3 + 0];
    float py = pos[(b * NN + m) * 3 + 1];
    float pz = pos[(b * NN + m) * 3 + 2];
    float rx = pos[(b * NN + n) * 3 + 0] - px;
    float ry = pos[(b * NN + n) * 3 + 1] - py;
    float rz = pos[(b * NN + n) * 3 + 2] - pz;

    float fu0[9], fu1[9];
    #pragma unroll
    for (int oo = 0; oo < 2; oo++) {
        int o = oo ? o1 : o0;
        float ox = g_ori[o * 3 + 0], oy = g_ori[o * 3 + 1], oz = g_ori[o * 3 + 2];
        float a = rx * ox + ry * oy + rz * oz;
        float vx = rx - rx * a;
        float vy = ry - ry * a;
        float vz = rz - rz * a;
        float bq = sqrtf(vx * vx + vy * vy + vz * vz);
        float* fu = oo ? fu1 : fu0;
        fu[0] = a;       fu[1] = bq;
        fu[2] = a * a;   fu[3] = a * bq;   fu[4] = bq * bq;
        fu[5] = fu[2] * a;  fu[6] = fu[2] * bq;  fu[7] = fu[3] * bq;  fu[8] = fu[4] * bq;
    }

    // packed accumulators: a0[d2] = (acc0[2*d2], acc0[2*d2+1]) etc.
    unsigned long long a0[16], a1[16];
    #pragma unroll
    for (int d2 = 0; d2 < 16; d2++) { a0[d2] = 0ull; a1[d2] = 0ull; }

    for (int j = 0; j < HH; j++) {
        float bv = bb1[j];
        const float4* wr = (const float4*)(w1c + j * 12);
        float4 wa = wr[0];
        float4 wb = wr[1];
        float  wc = w1c[j * 12 + 8];
        float t0 = bv + fu0[0] * wa.x + fu0[1] * wa.y + fu0[2] * wa.z + fu0[3] * wa.w
                      + fu0[4] * wb.x + fu0[5] * wb.y + fu0[6] * wb.z + fu0[7] * wb.w
                      + fu0[8] * wc;
        float t1 = bv + fu1[0] * wa.x + fu1[1] * wa.y + fu1[2] * wa.z + fu1[3] * wa.w
                      + fu1[4] * wb.x + fu1[5] * wb.y + fu1[6] * wb.z + fu1[7] * wb.w
                      + fu1[8] * wc;
        float h0 = gelu_f(t0);
        float h1 = gelu_f(t1);
        unsigned long long h0p = pack2(h0, h0);
        unsigned long long h1p = pack2(h1, h1);
        const ulonglong2* w2r = (const ulonglong2*)(w2 + j * BDQ);
        #pragma unroll
        for (int d4 = 0; d4 < 8; d4++) {
            ulonglong2 wv = w2r[d4];            // pairs (w[4d4],w[4d4+1]), (w[4d4+2],w[4d4+3])
            fma2(a0[2 * d4], h0p, wv.x);
            fma2(a0[2 * d4 + 1], h0p, wv.y);
            fma2(a1[2 * d4], h1p, wv.x);
            fma2(a1[2 * d4 + 1], h1p, wv.y);
        }
    }

    float accf0[BDQ], accf1[BDQ];
    #pragma unroll
    for (int d2 = 0; d2 < 16; d2++) {
        float2 u = unpack2(a0[d2]);
        accf0[2 * d2] = u.x; accf0[2 * d2 + 1] = u.y;
        float2 v = unpack2(a1[d2]);
        accf1[2 * d2] = v.x; accf1[2 * d2 + 1] = v.y;
    }

    size_t base0 = ((((size_t)b * NN + m) * OO + o0) * NN + n) * BDQ;
    size_t base1 = ((((size_t)b * NN + m) * OO + o1) * NN + n) * BDQ;
    float4* dst0 = (float4*)(g_kb + base0);
    float4* dst1 = (float4*)(g_kb + base1);
    #pragma unroll
    for (int d4 = 0; d4 < 8; d4++) {
        float4 v0, v1;
        v0.x = gelu_f(accf0[d4 * 4 + 0] + bb2[d4 * 4 + 0]);
        v0.y = gelu_f(accf0[d4 * 4 + 1] + bb2[d4 * 4 + 1]);
        v0.z = gelu_f(accf0[d4 * 4 + 2] + bb2[d4 * 4 + 2]);
        v0.w = gelu_f(accf0[d4 * 4 + 3] + bb2[d4 * 4 + 3]);
        v1.x = gelu_f(accf1[d4 * 4 + 0] + bb2[d4 * 4 + 0]);
        v1.y = gelu_f(accf1[d4 * 4 + 1] + bb2[d4 * 4 + 1]);
        v1.z = gelu_f(accf1[d4 * 4 + 2] + bb2[d4 * 4 + 2]);
        v1.w = gelu_f(accf1[d4 * 4 + 3] + bb2[d4 * 4 + 3]);
        dst0[d4] = v0;
        dst1[d4] = v1;
    }
}

// ---------------- kernel D: spatial conv (f32x2 + cp.async double buffer) ---
// Per nn: 8 LDS.128 + 16 FFMA2; kb tile staging via cp.async prefetch so the
// L2 latency of the next chunk overlaps compute of the current chunk.
__global__ void __launch_bounds__(128)
conv_kernel(const float* __restrict__ WspL, const float* __restrict__ mask) {
    int o = blockIdx.x, m = blockIdx.y, b = blockIdx.z;
    int c = threadIdx.x;

    __shared__ float msh[NN];
    __shared__ __align__(16) float kbs[2][32 * BDQ];   // double-buffered 4KB tiles

    msh[c] = mask[b * NN + c];
    unsigned long long wsp2[16];
    #pragma unroll
    for (int d2 = 0; d2 < 16; d2++)
        wsp2[d2] = pack2(WspL[(2 * d2) * HH + c], WspL[(2 * d2 + 1) * HH + c]);

    const float* kbp = g_kb + ((((size_t)b * NN + m) * OO + o) * NN) * BDQ;
    const float* hp  = g_h + ((size_t)(b * OO + o) * NN) * HH;

    uint32_t kbs_base = (uint32_t)__cvta_generic_to_shared(&kbs[0][0]);

    // stage chunk nc into buffer buf (each thread copies 2 x 16B of the 4KB tile)
    auto stage = [&](int buf, int nc) {
        uint32_t dst = kbs_base + buf * (32 * BDQ * 4) + c * 16;
        const char* src = (const char*)(kbp + nc * 32 * BDQ) + c * 16;
        cp_async16(dst, src);
        cp_async16(dst + 2048, src + 2048);
        cp_commit();
    };

    stage(0, 0);

    float acc = 0.0f;
    #pragma unroll
    for (int nc = 0; nc < 4; nc++) {
        int cur = nc & 1;
        if (nc < 3) stage(1 - cur, nc + 1);
        if (nc < 3) cp_wait<1>(); else cp_wait<0>();
        __syncthreads();
        #pragma unroll 4
        for (int nn = 0; nn < 32; nn++) {
            const ulonglong2* kr = (const ulonglong2*)(kbs[cur] + nn * BDQ);
            unsigned long long sa = 0ull, sb = 0ull;   // 2 chains for ILP
            #pragma unroll
            for (int d4 = 0; d4 < 8; d4++) {
                ulonglong2 kv = kr[d4];
                fma2(sa, kv.x, wsp2[2 * d4]);
                fma2(sb, kv.y, wsp2[2 * d4 + 1]);
            }
            float2 fa = unpack2(sa);
            float2 fb = unpack2(sb);
            float sk = (fa.x + fa.y) + (fb.x + fb.y);
            int n = nc * 32 + nn;
            acc += (hp[n * HH + c] * msh[n]) * sk;
        }
        __syncthreads();   // all threads done with kbs[cur] before it is re-staged
    }
    g_hc[((b * NN + m) * OO + o) * HH + c] = acc;
}

// ---------------- kernel E: rot mix + LN + MLP + residual (f32x2 MLP) -------
// grid (NN, BB, 2): each block handles 6 fiber points (ph*6 .. ph*6+5).
#define PH 6
__global__ void __launch_bounds__(128)
layer_kernel(const float* __restrict__ rotkL,
             const float* __restrict__ conv_bL, const float* __restrict__ ln_sL,
             const float* __restrict__ ln_bL,
             const float* __restrict__ Wl1L, const float* __restrict__ bl1L,
             const float* __restrict__ Wl2L, const float* __restrict__ bl2L) {
    int m = blockIdx.x, b = blockIdx.y, ph = blockIdx.z;
    int c = threadIdx.x;   // 128

    __shared__ float hc_sh[OO * HH];                 // 6 KB (all 12 o needed)
    __shared__ float us[PH * HH];                    // 3 KB
    __shared__ __align__(16) float v_sh[HH * 8];     // 4 KB  (c2-major, p padded to 8)
    __shared__ __align__(16) float g_sh[WFH * 8];    // 16 KB (j-major, p padded to 8)
    __shared__ float s_mean[PH], s_rstd[PH];

    const float* hcp = g_hc + (size_t)((b * NN + m) * OO) * HH;
    for (int i = c; i < OO * HH; i += 128) hc_sh[i] = hcp[i];
    __syncthreads();

    // rot mixing -> us (6 p's of this block)
    float cb = conv_bL[c];
    #pragma unroll
    for (int pl = 0; pl < PH; pl++) {
        int p = ph * PH + pl;
        float u = 0.0f;
        #pragma unroll
        for (int o = 0; o < OO; o++)
            u += hc_sh[o * HH + c] * rotkL[(p * OO + o) * HH + c];
        us[pl * HH + c] = u * (1.0f / 12.0f) + cb;
    }
    __syncthreads();

    // parallel LN stats over the 6 local p's
    {
        int w = c >> 5, lane = c & 31;
        for (int pl = w; pl < PH; pl += 4) {
            float v0 = us[pl * HH + lane];
            float v1 = us[pl * HH + lane + 32];
            float v2 = us[pl * HH + lane + 64];
            float v3 = us[pl * HH + lane + 96];
            float s1 = v0 + v1 + v2 + v3;
            float s2 = v0 * v0 + v1 * v1 + v2 * v2 + v3 * v3;
            #pragma unroll
            for (int off = 16; off; off >>= 1) {
                s1 += __shfl_down_sync(0xffffffffu, s1, off);
                s2 += __shfl_down_sync(0xffffffffu, s2, off);
            }
            if (lane == 0) {
                float mean = s1 * (1.0f / 128.0f);
                float var = s2 * (1.0f / 128.0f) - mean * mean;
                s_mean[pl] = mean;
                s_rstd[pl] = rsqrtf(var + 1e-6f);
            }
        }
    }
    __syncthreads();

    float lns = ln_sL[c], lnb = ln_bL[c];
    #pragma unroll
    for (int pl = 0; pl < PH; pl++) {
        float d = us[pl * HH + c] - s_mean[pl];
        v_sh[c * 8 + pl] = d * s_rstd[pl] * lns + lnb;
    }
    __syncthreads();

    // MLP layer 1: 128 -> 512 with gelu; thread owns j = jj*128+c
    // packed over p-pairs: 3 f32x2 chains
    for (int jj = 0; jj < 4; jj++) {
        int j = jj * 128 + c;
        float bv = bl1L[j];
        unsigned long long s2p[3];
        s2p[0] = pack2(bv, bv); s2p[1] = s2p[0]; s2p[2] = s2p[0];
        const float* wcol = Wl1L + j;
        for (int c2 = 0; c2 < HH; c2++) {
            float w = wcol[c2 * WFH];
            unsigned long long wp = pack2(w, w);
            const ulonglong2* vr2 = (const ulonglong2*)(v_sh + c2 * 8);
            ulonglong2 vab = vr2[0];                       // (p0,p1),(p2,p3)
            unsigned long long vc = ((const unsigned long long*)(v_sh + c2 * 8))[2]; // (p4,p5)
            fma2(s2p[0], vab.x, wp);
            fma2(s2p[1], vab.y, wp);
            fma2(s2p[2], vc, wp);
        }
        float2 r0 = unpack2(s2p[0]);
        float2 r1 = unpack2(s2p[1]);
        float2 r2 = unpack2(s2p[2]);
        g_sh[j * 8 + 0] = gelu_f(r0.x);
        g_sh[j * 8 + 1] = gelu_f(r0.y);
        g_sh[j * 8 + 2] = gelu_f(r1.x);
        g_sh[j * 8 + 3] = gelu_f(r1.y);
        g_sh[j * 8 + 4] = gelu_f(r2.x);
        g_sh[j * 8 + 5] = gelu_f(r2.y);
    }
    __syncthreads();

    // MLP layer 2: 512 -> 128, + residual into g_h (in place), packed p-pairs
    float bv2 = bl2L[c];
    unsigned long long y2[3];
    y2[0] = pack2(bv2, bv2); y2[1] = y2[0]; y2[2] = y2[0];
    const float* wcol2 = Wl2L + c;
    for (int j = 0; j < WFH; j++) {
        float w = wcol2[j * HH];
        unsigned long long wp = pack2(w, w);
        const ulonglong2* gr2 = (const ulonglong2*)(g_sh + j * 8);
        ulonglong2 gab = gr2[0];
        unsigned long long gc = ((const unsigned long long*)(g_sh + j * 8))[2];
        fma2(y2[0], gab.x, wp);
        fma2(y2[1], gab.y, wp);
        fma2(y2[2], gc, wp);
    }
    float y[PH];
    {
        float2 r0 = unpack2(y2[0]);
        float2 r1 = unpack2(y2[1]);
        float2 r2 = unpack2(y2[2]);
        y[0] = r0.x; y[1] = r0.y; y[2] = r1.x; y[3] = r1.y; y[4] = r2.x; y[5] = r2.y;
    }
    #pragma unroll
    for (int pl = 0; pl < PH; pl++) {
        int p = ph * PH + pl;
        size_t idx = (size_t)((b * OO + p) * NN + m) * HH + c;
        g_h[idx] = g_h[idx] + y[pl];
    }
}

// ---------------- kernel F: readout -----------------------------------------
__global__ void readout_kernel(const float* __restrict__ Wro, const float* __restrict__ bro,
                               const float* __restrict__ mask, float* __restrict__ out) {
    int b = blockIdx.x;
    int n = threadIdx.x;   // 128
    __shared__ __align__(16) float wro_sh[HH];
    __shared__ float red[32];
    wro_sh[n] = Wro[n];
    __syncthreads();

    float s = 0.0f;
    for (int o = 0; o < OO; o++) {
        const float4* hp = (const float4*)(g_h + (size_t)((b * OO + o) * NN + n) * HH);
        const float4* wp = (const float4*)wro_sh;
        float t = 0.0f;
        #pragma unroll
        for (int i = 0; i < 32; i++) {
            float4 hv = hp[i];
            float4 wv = wp[i];
            t += hv.x * wv.x + hv.y * wv.y + hv.z * wv.z + hv.w * wv.w;
        }
        s += t;
    }
    float r = s * (1.0f / 12.0f) + bro[0];
    float mk = mask[b * NN + n];
    float num = blockReduceSum128(r * mk, red);
    float den = blockReduceSum128(mk, red);
    if (n == 0) out[b] = num / den;
}

// ---------------- launch -----------------------------------------------------
extern "C" void kernel_launch(void* const* d_in, const int* in_sizes, int n_in,
                              void* d_out, int out_size) {
    const float* pos      = (const float*)d_in[0];
    const float* x        = (const float*)d_in[1];
    const float* mask     = (const float*)d_in[2];
    const float* W1s      = (const float*)d_in[3];
    const float* b1s      = (const float*)d_in[4];
    const float* W2s      = (const float*)d_in[5];
    const float* b2s      = (const float*)d_in[6];
    const float* W1r      = (const float*)d_in[7];
    const float* b1r      = (const float*)d_in[8];
    const float* W2r      = (const float*)d_in[9];
    const float* b2r      = (const float*)d_in[10];
    const float* We       = (const float*)d_in[11];
    const float* Wsp      = (const float*)d_in[12];
    const float* Wrot     = (const float*)d_in[13];
    const float* conv_b   = (const float*)d_in[14];
    const float* ln_scale = (const float*)d_in[15];
    const float* ln_bias  = (const float*)d_in[16];
    const float* Wl1      = (const float*)d_in[17];
    const float* bl1      = (const float*)d_in[18];
    const float* Wl2      = (const float*)d_in[19];
    const float* bl2      = (const float*)d_in[20];
    const float* Wro      = (const float*)d_in[21];
    const float* bro      = (const float*)d_in[22];
    float* out = (float*)d_out;

    float* rotk_dev = nullptr;
    cudaGetSymbolAddress((void**)&rotk_dev, g_rotk);

    setup_kernel<<<1, 256>>>(W1r, b1r, W2r, b2r, Wrot);
    embed_kernel<<<dim3(NN, BB), 128>>>(x, We);
    kbasis_kernel<<<dim3(OO / 2, NN, BB), 128>>>(pos, W1s, b1s, W2s, b2s);

    for (int l = 0; l < LL; l++) {
        conv_kernel<<<dim3(OO, NN, BB), 128>>>(Wsp + l * BDQ * HH, mask);
        layer_kernel<<<dim3(NN, BB, 2), 128>>>(rotk_dev + l * OO * OO * HH,
                                               conv_b + l * HH,
                                               ln_scale + l * HH, ln_bias + l * HH,
                                               Wl1 + l * HH * WFH, bl1 + l * WFH,
                                               Wl2 + l * WFH * HH, bl2 + l * HH);
    }

    readout_kernel<<<BB, 128>>>(Wro, bro, mask, out);
}

// round 16
// speedup vs baseline: 1.0161x; 1.0161x over previous
#include <cuda_runtime.h>
#include <math.h>
#include <cstdint>

#define BB 2
#define NN 128
#define HH 128
#define OO 12
#define BDQ 32
#define LL 2
#define WFH 512
#define INQ 16

// ---------------- scratch (static device globals; no allocation) ------------
__device__ float g_ori[OO * 3];
__device__ float g_rotk[LL * OO * OO * HH];            // (L,P,O,H)
__device__ float g_h[BB * OO * NN * HH];               // (B,O,N,H) feature state
__device__ float g_hc[BB * NN * OO * HH];              // (B,M,O,H) conv output
__device__ float g_kb[(size_t)BB * NN * OO * NN * BDQ]; // (B,M,O,N,BD) ~50MB

// exact gelu (setup only, cold path)
__device__ __forceinline__ float gelu_exact(float x) {
    float x3 = x * x * x;
    float t = tanhf(0.7978845608028654f * (x + 0.044715f * x3));
    return 0.5f * x * (1.0f + t);
}

// fast gelu: MUFU tanh.approx (measured rel_err impact ~3e-7 end-to-end)
__device__ __forceinline__ float gelu_f(float x) {
    float x3 = x * x * x;
    float a = 0.7978845608028654f * (x + 0.044715f * x3);
    float t;
    asm("tanh.approx.f32 %0, %1;" : "=f"(t) : "f"(a));
    return 0.5f * x * (1.0f + t);
}

// ---- packed f32x2 helpers (FFMA2 path; ptxas won't emit from C++) ----------
__device__ __forceinline__ void fma2(unsigned long long& acc,
                                     unsigned long long a, unsigned long long b) {
    asm("fma.rn.f32x2 %0, %1, %2, %0;" : "+l"(acc) : "l"(a), "l"(b));
}
__device__ __forceinline__ unsigned long long pack2(float lo, float hi) {
    unsigned long long r;
    asm("mov.b64 %0, {%1, %2};" : "=l"(r) : "f"(lo), "f"(hi));
    return r;
}
__device__ __forceinline__ float2 unpack2(unsigned long long v) {
    float lo, hi;
    asm("mov.b64 {%0, %1}, %2;" : "=f"(lo), "=f"(hi) : "l"(v));
    return make_float2(lo, hi);
}

__device__ __forceinline__ float blockReduceSum128(float val, float* red) {
    #pragma unroll
    for (int off = 16; off; off >>= 1)
        val += __shfl_down_sync(0xffffffffu, val, off);
    __syncthreads();
    if ((threadIdx.x & 31) == 0) red[threadIdx.x >> 5] = val;
    __syncthreads();
    return red[0] + red[1] + red[2] + red[3];
}

// ---------------- kernel A: ori, fiber basis, rot kernels -------------------
__global__ void setup_kernel(const float* __restrict__ W1r, const float* __restrict__ b1r,
                             const float* __restrict__ W2r, const float* __restrict__ b2r,
                             const float* __restrict__ Wrot) {
    __shared__ float fb_sh[OO * OO * BDQ];   // fiber basis (P,O,BD)
    int t = threadIdx.x;                     // 256 threads

    if (t < OO) {
        float fi = (float)t;
        const float PI_F  = 3.14159265358979323846f;
        const float C_F   = 3.23606797749978969641f;   // 1+sqrt(5) in f32
        const float TWOPI = 6.28318530717958647692f;
        float theta = fmodf((PI_F * fi) * C_F, TWOPI);
        float phi = acosf(1.0f - 2.0f * (fi + 0.5f) / 12.0f);
        float sp = sinf(phi);
        g_ori[t * 3 + 0] = sp * cosf(theta);
        g_ori[t * 3 + 1] = sp * sinf(theta);
        g_ori[t * 3 + 2] = cosf(phi);
    }
    __syncthreads();

    if (t < OO * OO) {
        int p = t / OO, o = t % OO;
        float tt = g_ori[p * 3 + 0] * g_ori[o * 3 + 0]
                 + g_ori[p * 3 + 1] * g_ori[o * 3 + 1]
                 + g_ori[p * 3 + 2] * g_ori[o * 3 + 2];
        float f0 = tt, f1 = tt * tt, f2 = f1 * tt;
        float acc[BDQ];
        #pragma unroll
        for (int d = 0; d < BDQ; d++) acc[d] = 0.0f;
        for (int j = 0; j < HH; j++) {
            float hj = gelu_exact(b1r[j] + f0 * W1r[0 * HH + j]
                                         + f1 * W1r[1 * HH + j]
                                         + f2 * W1r[2 * HH + j]);
            #pragma unroll
            for (int d = 0; d < BDQ; d++) acc[d] += hj * W2r[j * BDQ + d];
        }
        #pragma unroll
        for (int d = 0; d < BDQ; d++)
            fb_sh[t * BDQ + d] = gelu_exact(acc[d] + b2r[d]);
    }
    __syncthreads();

    for (int idx = t; idx < LL * OO * OO * HH; idx += blockDim.x) {
        int c = idx % HH;
        int rest = idx / HH;
        int o = rest % OO; rest /= OO;
        int p = rest % OO;
        int l = rest / OO;
        float s = 0.0f;
        #pragma unroll
        for (int d = 0; d < BDQ; d++)
            s += fb_sh[(p * OO + o) * BDQ + d] * Wrot[(l * BDQ + d) * HH + c];
        g_rotk[idx] = s;
    }
}

// ---------------- kernel B: h0 = x @ We, broadcast over O -------------------
__global__ void embed_kernel(const float* __restrict__ x, const float* __restrict__ We) {
    int n = blockIdx.x, b = blockIdx.y, c = threadIdx.x;
    __shared__ float xs[INQ];
    if (c < INQ) xs[c] = x[(b * NN + n) * INQ + c];
    __syncthreads();
    float s = 0.0f;
    #pragma unroll
    for (int k = 0; k < INQ; k++) s += xs[k] * We[k * HH + c];
    #pragma unroll
    for (int o = 0; o < OO; o++)
        g_h[((b * OO + o) * NN + n) * HH + c] = s;
}

// ---------------- kernel C: kernel basis MLP (2 o per block, f32x2 acc) -----
__global__ void __launch_bounds__(128)
kbasis_kernel(const float* __restrict__ pos,
              const float* __restrict__ W1s, const float* __restrict__ b1s,
              const float* __restrict__ W2s, const float* __restrict__ b2s) {
    int op = blockIdx.x, m = blockIdx.y, b = blockIdx.z;
    int o0 = op * 2, o1 = op * 2 + 1;
    int n = threadIdx.x;

    __shared__ __align__(16) float w1c[HH * 12];   // folded weights, 12-padded
    __shared__ float bb1[HH];
    __shared__ __align__(16) float w2[HH * BDQ];
    __shared__ float bb2[BDQ];

    // fold W1s (14 x 128) -> w1c (128 x 9, pad 12); thread n owns row j=n
    {
        int j = n;
        w1c[j * 12 + 0] = W1s[0 * HH + j];                                   // a
        w1c[j * 12 + 1] = W1s[1 * HH + j];                                   // b
        w1c[j * 12 + 2] = W1s[2 * HH + j];                                   // a^2
        w1c[j * 12 + 3] = W1s[3 * HH + j] + W1s[4 * HH + j];                 // ab (+ba)
        w1c[j * 12 + 4] = W1s[5 * HH + j];                                   // b^2
        w1c[j * 12 + 5] = W1s[6 * HH + j];                                   // a^3
        w1c[j * 12 + 6] = W1s[7 * HH + j] + W1s[8 * HH + j] + W1s[10 * HH + j];  // a^2 b
        w1c[j * 12 + 7] = W1s[9 * HH + j] + W1s[11 * HH + j] + W1s[12 * HH + j]; // a b^2
        w1c[j * 12 + 8] = W1s[13 * HH + j];                                  // b^3
        w1c[j * 12 + 9] = 0.0f; w1c[j * 12 + 10] = 0.0f; w1c[j * 12 + 11] = 0.0f;
    }
    bb1[n] = b1s[n];
    for (int i = n; i < HH * BDQ; i += 128) w2[i] = W2s[i];
    if (n < BDQ) bb2[n] = b2s[n];
    __syncthreads();

    float px = pos[(b * NN + m) * 3 + 0];
    float py = pos[(b * NN + m) * 3 + 1];
    float pz = pos[(b * NN + m) * 3 + 2];
    float rx = pos[(b * NN + n) * 3 + 0] - px;
    float ry = pos[(b * NN + n) * 3 + 1] - py;
    float rz = pos[(b * NN + n) * 3 + 2] - pz;

    float fu0[9], fu1[9];
    #pragma unroll
    for (int oo = 0; oo < 2; oo++) {
        int o = oo ? o1 : o0;
        float ox = g_ori[o * 3 + 0], oy = g_ori[o * 3 + 1], oz = g_ori[o * 3 + 2];
        float a = rx * ox + ry * oy + rz * oz;
        float vx = rx - rx * a;
        float vy = ry - ry * a;
        float vz = rz - rz * a;
        float bq = sqrtf(vx * vx + vy * vy + vz * vz);
        float* fu = oo ? fu1 : fu0;
        fu[0] = a;       fu[1] = bq;
        fu[2] = a * a;   fu[3] = a * bq;   fu[4] = bq * bq;
        fu[5] = fu[2] * a;  fu[6] = fu[2] * bq;  fu[7] = fu[3] * bq;  fu[8] = fu[4] * bq;
    }

    // packed accumulators: a0[d2] = (acc0[2*d2], acc0[2*d2+1]) etc.
    unsigned long long a0[16], a1[16];
    #pragma unroll
    for (int d2 = 0; d2 < 16; d2++) { a0[d2] = 0ull; a1[d2] = 0ull; }

    for (int j = 0; j < HH; j++) {
        float bv = bb1[j];
        const float4* wr = (const float4*)(w1c + j * 12);
        float4 wa = wr[0];
        float4 wb = wr[1];
        float  wc = w1c[j * 12 + 8];
        float t0 = bv + fu0[0] * wa.x + fu0[1] * wa.y + fu0[2] * wa.z + fu0[3] * wa.w
                      + fu0[4] * wb.x + fu0[5] * wb.y + fu0[6] * wb.z + fu0[7] * wb.w
                      + fu0[8] * wc;
        float t1 = bv + fu1[0] * wa.x + fu1[1] * wa.y + fu1[2] * wa.z + fu1[3] * wa.w
                      + fu1[4] * wb.x + fu1[5] * wb.y + fu1[6] * wb.z + fu1[7] * wb.w
                      + fu1[8] * wc;
        float h0 = gelu_f(t0);
        float h1 = gelu_f(t1);
        unsigned long long h0p = pack2(h0, h0);
        unsigned long long h1p = pack2(h1, h1);
        const ulonglong2* w2r = (const ulonglong2*)(w2 + j * BDQ);
        #pragma unroll
        for (int d4 = 0; d4 < 8; d4++) {
            ulonglong2 wv = w2r[d4];            // pairs (w[4d4],w[4d4+1]), (w[4d4+2],w[4d4+3])
            fma2(a0[2 * d4], h0p, wv.x);
            fma2(a0[2 * d4 + 1], h0p, wv.y);
            fma2(a1[2 * d4], h1p, wv.x);
            fma2(a1[2 * d4 + 1], h1p, wv.y);
        }
    }

    float accf0[BDQ], accf1[BDQ];
    #pragma unroll
    for (int d2 = 0; d2 < 16; d2++) {
        float2 u = unpack2(a0[d2]);
        accf0[2 * d2] = u.x; accf0[2 * d2 + 1] = u.y;
        float2 v = unpack2(a1[d2]);
        accf1[2 * d2] = v.x; accf1[2 * d2 + 1] = v.y;
    }

    size_t base0 = ((((size_t)b * NN + m) * OO + o0) * NN + n) * BDQ;
    size_t base1 = ((((size_t)b * NN + m) * OO + o1) * NN + n) * BDQ;
    float4* dst0 = (float4*)(g_kb + base0);
    float4* dst1 = (float4*)(g_kb + base1);
    #pragma unroll
    for (int d4 = 0; d4 < 8; d4++) {
        float4 v0, v1;
        v0.x = gelu_f(accf0[d4 * 4 + 0] + bb2[d4 * 4 + 0]);
        v0.y = gelu_f(accf0[d4 * 4 + 1] + bb2[d4 * 4 + 1]);
        v0.z = gelu_f(accf0[d4 * 4 + 2] + bb2[d4 * 4 + 2]);
        v0.w = gelu_f(accf0[d4 * 4 + 3] + bb2[d4 * 4 + 3]);
        v1.x = gelu_f(accf1[d4 * 4 + 0] + bb2[d4 * 4 + 0]);
        v1.y = gelu_f(accf1[d4 * 4 + 1] + bb2[d4 * 4 + 1]);
        v1.z = gelu_f(accf1[d4 * 4 + 2] + bb2[d4 * 4 + 2]);
        v1.w = gelu_f(accf1[d4 * 4 + 3] + bb2[d4 * 4 + 3]);
        dst0[d4] = v0;
        dst1[d4] = v1;
    }
}

// ---------------- kernel D: spatial conv (per layer, f32x2 inner) -----------
// R10 proven form: per nn 8 LDS.128 + 16 FFMA2; reg-staged tiles (measured
// 101.7us/layer; cp.async variant measured slower -> reverted).
__global__ void __launch_bounds__(128)
conv_kernel(const float* __restrict__ WspL, const float* __restrict__ mask) {
    int o = blockIdx.x, m = blockIdx.y, b = blockIdx.z;
    int c = threadIdx.x;

    __shared__ float msh[NN];
    __shared__ __align__(16) float kbs[32 * BDQ];   // 32 n x 32 d tile

    msh[c] = mask[b * NN + c];
    unsigned long long wsp2[16];
    #pragma unroll
    for (int d2 = 0; d2 < 16; d2++)
        wsp2[d2] = pack2(WspL[(2 * d2) * HH + c], WspL[(2 * d2 + 1) * HH + c]);

    const float* kbp = g_kb + ((((size_t)b * NN + m) * OO + o) * NN) * BDQ;
    const float* hp  = g_h + ((size_t)(b * OO + o) * NN) * HH;

    float acc = 0.0f;
    for (int nc = 0; nc < 4; nc++) {
        __syncthreads();
        const float4* g4 = (const float4*)(kbp + nc * 32 * BDQ);
        float4* s4 = (float4*)kbs;
        s4[c] = g4[c];
        s4[c + 128] = g4[c + 128];
        __syncthreads();
        #pragma unroll 4
        for (int nn = 0; nn < 32; nn++) {
            const ulonglong2* kr = (const ulonglong2*)(kbs + nn * BDQ);
            unsigned long long sa = 0ull, sb = 0ull;   // 2 chains for ILP
            #pragma unroll
            for (int d4 = 0; d4 < 8; d4++) {
                ulonglong2 kv = kr[d4];
                fma2(sa, kv.x, wsp2[2 * d4]);
                fma2(sb, kv.y, wsp2[2 * d4 + 1]);
            }
            float2 fa = unpack2(sa);
            float2 fb = unpack2(sb);
            float sk = (fa.x + fa.y) + (fb.x + fb.y);
            int n = nc * 32 + nn;
            acc += (hp[n * HH + c] * msh[n]) * sk;
        }
    }
    g_hc[((b * NN + m) * OO + o) * HH + c] = acc;
}

// ---------------- kernel E: rot mix + LN + MLP + residual (f32x2 MLP) -------
// grid (NN, BB, 2): each block handles 6 fiber points (ph*6 .. ph*6+5).
#define PH 6
__global__ void __launch_bounds__(128)
layer_kernel(const float* __restrict__ rotkL,
             const float* __restrict__ conv_bL, const float* __restrict__ ln_sL,
             const float* __restrict__ ln_bL,
             const float* __restrict__ Wl1L, const float* __restrict__ bl1L,
             const float* __restrict__ Wl2L, const float* __restrict__ bl2L) {
    int m = blockIdx.x, b = blockIdx.y, ph = blockIdx.z;
    int c = threadIdx.x;   // 128

    __shared__ float hc_sh[OO * HH];                 // 6 KB (all 12 o needed)
    __shared__ float us[PH * HH];                    // 3 KB
    __shared__ __align__(16) float v_sh[HH * 8];     // 4 KB  (c2-major, p padded to 8)
    __shared__ __align__(16) float g_sh[WFH * 8];    // 16 KB (j-major, p padded to 8)
    __shared__ float s_mean[PH], s_rstd[PH];

    const float* hcp = g_hc + (size_t)((b * NN + m) * OO) * HH;
    for (int i = c; i < OO * HH; i += 128) hc_sh[i] = hcp[i];
    __syncthreads();

    // rot mixing -> us (6 p's of this block)
    float cb = conv_bL[c];
    #pragma unroll
    for (int pl = 0; pl < PH; pl++) {
        int p = ph * PH + pl;
        float u = 0.0f;
        #pragma unroll
        for (int o = 0; o < OO; o++)
            u += hc_sh[o * HH + c] * rotkL[(p * OO + o) * HH + c];
        us[pl * HH + c] = u * (1.0f / 12.0f) + cb;
    }
    __syncthreads();

    // parallel LN stats over the 6 local p's
    {
        int w = c >> 5, lane = c & 31;
        for (int pl = w; pl < PH; pl += 4) {
            float v0 = us[pl * HH + lane];
            float v1 = us[pl * HH + lane + 32];
            float v2 = us[pl * HH + lane + 64];
            float v3 = us[pl * HH + lane + 96];
            float s1 = v0 + v1 + v2 + v3;
            float s2 = v0 * v0 + v1 * v1 + v2 * v2 + v3 * v3;
            #pragma unroll
            for (int off = 16; off; off >>= 1) {
                s1 += __shfl_down_sync(0xffffffffu, s1, off);
                s2 += __shfl_down_sync(0xffffffffu, s2, off);
            }
            if (lane == 0) {
                float mean = s1 * (1.0f / 128.0f);
                float var = s2 * (1.0f / 128.0f) - mean * mean;
                s_mean[pl] = mean;
                s_rstd[pl] = rsqrtf(var + 1e-6f);
            }
        }
    }
    __syncthreads();

    float lns = ln_sL[c], lnb = ln_bL[c];
    #pragma unroll
    for (int pl = 0; pl < PH; pl++) {
        float d = us[pl * HH + c] - s_mean[pl];
        v_sh[c * 8 + pl] = d * s_rstd[pl] * lns + lnb;
    }
    __syncthreads();

    // MLP layer 1: 128 -> 512 with gelu; thread owns j = jj*128+c
    // packed over p-pairs: 3 f32x2 chains
    for (int jj = 0; jj < 4; jj++) {
        int j = jj * 128 + c;
        float bv = bl1L[j];
        unsigned long long s2p[3];
        s2p[0] = pack2(bv, bv); s2p[1] = s2p[0]; s2p[2] = s2p[0];
        const float* wcol = Wl1L + j;
        for (int c2 = 0; c2 < HH; c2++) {
            float w = wcol[c2 * WFH];
            unsigned long long wp = pack2(w, w);
            const ulonglong2* vr2 = (const ulonglong2*)(v_sh + c2 * 8);
            ulonglong2 vab = vr2[0];                       // (p0,p1),(p2,p3)
            unsigned long long vc = ((const unsigned long long*)(v_sh + c2 * 8))[2]; // (p4,p5)
            fma2(s2p[0], vab.x, wp);
            fma2(s2p[1], vab.y, wp);
            fma2(s2p[2], vc, wp);
        }
        float2 r0 = unpack2(s2p[0]);
        float2 r1 = unpack2(s2p[1]);
        float2 r2 = unpack2(s2p[2]);
        g_sh[j * 8 + 0] = gelu_f(r0.x);
        g_sh[j * 8 + 1] = gelu_f(r0.y);
        g_sh[j * 8 + 2] = gelu_f(r1.x);
        g_sh[j * 8 + 3] = gelu_f(r1.y);
        g_sh[j * 8 + 4] = gelu_f(r2.x);
        g_sh[j * 8 + 5] = gelu_f(r2.y);
    }
    __syncthreads();

    // MLP layer 2: 512 -> 128, + residual into g_h (in place), packed p-pairs
    float bv2 = bl2L[c];
    unsigned long long y2[3];
    y2[0] = pack2(bv2, bv2); y2[1] = y2[0]; y2[2] = y2[0];
    const float* wcol2 = Wl2L + c;
    for (int j = 0; j < WFH; j++) {
        float w = wcol2[j * HH];
        unsigned long long wp = pack2(w, w);
        const ulonglong2* gr2 = (const ulonglong2*)(g_sh + j * 8);
        ulonglong2 gab = gr2[0];
        unsigned long long gc = ((const unsigned long long*)(g_sh + j * 8))[2];
        fma2(y2[0], gab.x, wp);
        fma2(y2[1], gab.y, wp);
        fma2(y2[2], gc, wp);
    }
    float y[PH];
    {
        float2 r0 = unpack2(y2[0]);
        float2 r1 = unpack2(y2[1]);
        float2 r2 = unpack2(y2[2]);
        y[0] = r0.x; y[1] = r0.y; y[2] = r1.x; y[3] = r1.y; y[4] = r2.x; y[5] = r2.y;
    }
    #pragma unroll
    for (int pl = 0; pl < PH; pl++) {
        int p = ph * PH + pl;
        size_t idx = (size_t)((b * OO + p) * NN + m) * HH + c;
        g_h[idx] = g_h[idx] + y[pl];
    }
}

// ---------------- kernel F: readout -----------------------------------------
__global__ void readout_kernel(const float* __restrict__ Wro, const float* __restrict__ bro,
                               const float* __restrict__ mask, float* __restrict__ out) {
    int b = blockIdx.x;
    int n = threadIdx.x;   // 128
    __shared__ __align__(16) float wro_sh[HH];
    __shared__ float red[32];
    wro_sh[n] = Wro[n];
    __syncthreads();

    float s = 0.0f;
    for (int o = 0; o < OO; o++) {
        const float4* hp = (const float4*)(g_h + (size_t)((b * OO + o) * NN + n) * HH);
        const float4* wp = (const float4*)wro_sh;
        float t = 0.0f;
        #pragma unroll
        for (int i = 0; i < 32; i++) {
            float4 hv = hp[i];
            float4 wv = wp[i];
            t += hv.x * wv.x + hv.y * wv.y + hv.z * wv.z + hv.w * wv.w;
        }
        s += t;
    }
    float r = s * (1.0f / 12.0f) + bro[0];
    float mk = mask[b * NN + n];
    float num = blockReduceSum128(r * mk, red);
    float den = blockReduceSum128(mk, red);
    if (n == 0) out[b] = num / den;
}

// ---------------- launch -----------------------------------------------------
extern "C" void kernel_launch(void* const* d_in, const int* in_sizes, int n_in,
                              void* d_out, int out_size) {
    const float* pos      = (const float*)d_in[0];
    const float* x        = (const float*)d_in[1];
    const float* mask     = (const float*)d_in[2];
    const float* W1s      = (const float*)d_in[3];
    const float* b1s      = (const float*)d_in[4];
    const float* W2s      = (const float*)d_in[5];
    const float* b2s      = (const float*)d_in[6];
    const float* W1r      = (const float*)d_in[7];
    const float* b1r      = (const float*)d_in[8];
    const float* W2r      = (const float*)d_in[9];
    const float* b2r      = (const float*)d_in[10];
    const float* We       = (const float*)d_in[11];
    const float* Wsp      = (const float*)d_in[12];
    const float* Wrot     = (const float*)d_in[13];
    const float* conv_b   = (const float*)d_in[14];
    const float* ln_scale = (const float*)d_in[15];
    const float* ln_bias  = (const float*)d_in[16];
    const float* Wl1      = (const float*)d_in[17];
    const float* bl1      = (const float*)d_in[18];
    const float* Wl2      = (const float*)d_in[19];
    const float* bl2      = (const float*)d_in[20];
    const float* Wro      = (const float*)d_in[21];
    const float* bro      = (const float*)d_in[22];
    float* out = (float*)d_out;

    float* rotk_dev = nullptr;
    cudaGetSymbolAddress((void**)&rotk_dev, g_rotk);

    setup_kernel<<<1, 256>>>(W1r, b1r, W2r, b2r, Wrot);
    embed_kernel<<<dim3(NN, BB), 128>>>(x, We);
    kbasis_kernel<<<dim3(OO / 2, NN, BB), 128>>>(pos, W1s, b1s, W2s, b2s);

    for (int l = 0; l < LL; l++) {
        conv_kernel<<<dim3(OO, NN, BB), 128>>>(Wsp + l * BDQ * HH, mask);
        layer_kernel<<<dim3(NN, BB, 2), 128>>>(rotk_dev + l * OO * OO * HH,
                                               conv_b + l * HH,
                                               ln_scale + l * HH, ln_bias + l * HH,
                                               Wl1 + l * HH * WFH, bl1 + l * WFH,
                                               Wl2 + l * WFH * HH, bl2 + l * HH);
    }

    readout_kernel<<<BB, 128>>>(Wro, bro, mask, out);
}